// round 14
// baseline (speedup 1.0000x reference)
#include <cuda_runtime.h>
#include <cuda_fp16.h>
#include <math.h>

#define Tl 1024
#define Sl 1024
#define Bb 4
#define Ee 1024
#define Hh 16
#define Dd 64
#define AW_OFF 4194304   // T*B*E

// scratch (device globals) — all fp16
__device__ __half g_q[4096 * 1024];
__device__ __half g_k[4096 * 1024];
__device__ __half g_v[4096 * 1024];
__device__ __half g_x[4096 * 1024];
__device__ __half g_p[64 * 1024 * 1024];  // unnormalized probs [BH][T][S]
__device__ float  g_rs[64 * 1024];        // 1/rowsum [BH][T]

// side stream + events for aw overlap
namespace {
struct StreamInit {
    cudaStream_t s2;
    cudaEvent_t fork, join;
    StreamInit() {
        cudaStreamCreateWithFlags(&s2, cudaStreamNonBlocking);
        cudaEventCreateWithFlags(&fork, cudaEventDisableTiming);
        cudaEventCreateWithFlags(&join, cudaEventDisableTiming);
    }
};
StreamInit g_sx;
}

// ---------------------------------------------------------------------------
__device__ __forceinline__ void mma_f16(float c[4], const unsigned a[4],
                                        const unsigned b[2]) {
    asm volatile(
        "mma.sync.aligned.m16n8k16.row.col.f32.f16.f16.f32 "
        "{%0,%1,%2,%3},{%4,%5,%6,%7},{%8,%9},{%0,%1,%2,%3};"
        : "+f"(c[0]), "+f"(c[1]), "+f"(c[2]), "+f"(c[3])
        : "r"(a[0]), "r"(a[1]), "r"(a[2]), "r"(a[3]), "r"(b[0]), "r"(b[1]));
}
__device__ __forceinline__ unsigned h2u(__half2 h) {
    return *reinterpret_cast<unsigned*>(&h);
}

// Fast exp on the FMA/ALU pipes (no MUFU). Range-reduce by ln2, degree-4
// poly on f in [-0.347, 0.347] (max rel err ~4e-5), 2^j via exponent add.
// bits(12582912) = 0x4B400000 has 9 trailing zero bits, so (ji<<23) == j<<23.
__device__ __forceinline__ float fexp(float x) {
    float t = fmaf(x, 1.4426950409f, 12582912.0f);
    int ji = __float_as_int(t);
    float j = t - 12582912.0f;
    float f = fmaf(j, -0.6931471806f, x);
    float p = fmaf(f, 0.041666667f, 0.16666667f);
    p = fmaf(f, p, 0.5f);
    p = fmaf(f, p, 1.0f);
    p = fmaf(f, p, 1.0f);
    return __int_as_float(__float_as_int(p) + (ji << 23));
}

// ---------------------------------------------------------------------------
// fp16 GEMM 128x128xK(1024), 256 threads = 8 warps (2m x 4n), warp 64x32.
// ---------------------------------------------------------------------------
#define HPW 40
#define HBUF (128 * HPW)

template<bool AHALF, bool HOUT>
__device__ __forceinline__ void gemm128h(
    const float* __restrict__ Af, const __half* __restrict__ Ah,
    const float* __restrict__ W, const float* __restrict__ bias,
    __half* __restrict__ Ch, float* __restrict__ Cf,
    float scale, int m0, int n0, __half* smem)
{
    __half* As = smem;                 // [2][HBUF]
    __half* Ws = smem + 2 * HBUF;      // [2][HBUF]

    int tid = threadIdx.x, lane = tid & 31, wid = tid >> 5;
    int gi = lane >> 2, ti = lane & 3;
    int wm = (wid >> 2) * 64, wn = (wid & 3) * 32;
    int lr = tid >> 3, lc = (tid & 7) * 4;

    float acc[4][4][4];
#pragma unroll
    for (int mt = 0; mt < 4; mt++)
#pragma unroll
        for (int nt = 0; nt < 4; nt++)
#pragma unroll
            for (int r = 0; r < 4; r++) acc[mt][nt][r] = 0.f;

    const float* Wg = W + (size_t)(n0 + lr) * 1024 + lc;

    float4 ra[4]; uint4 rah[2]; float4 rw[4];
    if (!AHALF) {
#pragma unroll
        for (int i = 0; i < 4; i++)
            ra[i] = *(const float4*)(Af + (size_t)(m0 + lr + 32 * i) * 1024 + lc);
    } else {
#pragma unroll
        for (int i = 0; i < 2; i++) {
            int c = i * 256 + tid;
            int r = c >> 2, o8 = (c & 3) * 8;
            rah[i] = *(const uint4*)(Ah + (size_t)(m0 + r) * 1024 + o8);
        }
    }
#pragma unroll
    for (int i = 0; i < 4; i++)
        rw[i] = *(const float4*)(Wg + (size_t)i * 32 * 1024);

    if (!AHALF) {
#pragma unroll
        for (int i = 0; i < 4; i++) {
            __half2 h0 = __floats2half2_rn(ra[i].x, ra[i].y);
            __half2 h1 = __floats2half2_rn(ra[i].z, ra[i].w);
            uint2 u = make_uint2(h2u(h0), h2u(h1));
            *(uint2*)(As + (lr + 32 * i) * HPW + lc) = u;
        }
    } else {
#pragma unroll
        for (int i = 0; i < 2; i++) {
            int c = i * 256 + tid;
            int r = c >> 2, o8 = (c & 3) * 8;
            *(uint4*)(As + r * HPW + o8) = rah[i];
        }
    }
#pragma unroll
    for (int i = 0; i < 4; i++) {
        __half2 h0 = __floats2half2_rn(rw[i].x, rw[i].y);
        __half2 h1 = __floats2half2_rn(rw[i].z, rw[i].w);
        uint2 u = make_uint2(h2u(h0), h2u(h1));
        *(uint2*)(Ws + (lr + 32 * i) * HPW + lc) = u;
    }
    __syncthreads();

#pragma unroll 2
    for (int it = 0; it < 32; ++it) {
        if (it < 31) {
            if (!AHALF) {
#pragma unroll
                for (int i = 0; i < 4; i++)
                    ra[i] = *(const float4*)(Af + (size_t)(m0 + lr + 32 * i) * 1024 + (it + 1) * 32 + lc);
            } else {
#pragma unroll
                for (int i = 0; i < 2; i++) {
                    int c = i * 256 + tid;
                    int r = c >> 2, o8 = (c & 3) * 8;
                    rah[i] = *(const uint4*)(Ah + (size_t)(m0 + r) * 1024 + (it + 1) * 32 + o8);
                }
            }
#pragma unroll
            for (int i = 0; i < 4; i++)
                rw[i] = *(const float4*)(Wg + (size_t)i * 32 * 1024 + (it + 1) * 32);
        }
        const __half* a_s = As + (it & 1) * HBUF + wm * HPW;
        const __half* b_s = Ws + (it & 1) * HBUF + wn * HPW;
#pragma unroll
        for (int kk = 0; kk < 2; kk++) {
            unsigned af[4][4], bf[4][2];
#pragma unroll
            for (int mt = 0; mt < 4; mt++) {
                const __half* p = a_s + (mt * 16 + gi) * HPW + kk * 16 + 2 * ti;
                af[mt][0] = *(const unsigned*)(p);
                af[mt][1] = *(const unsigned*)(p + 8 * HPW);
                af[mt][2] = *(const unsigned*)(p + 8);
                af[mt][3] = *(const unsigned*)(p + 8 * HPW + 8);
            }
#pragma unroll
            for (int nt = 0; nt < 4; nt++) {
                const __half* p = b_s + (nt * 8 + gi) * HPW + kk * 16 + 2 * ti;
                bf[nt][0] = *(const unsigned*)(p);
                bf[nt][1] = *(const unsigned*)(p + 8);
            }
#pragma unroll
            for (int mt = 0; mt < 4; mt++)
#pragma unroll
                for (int nt = 0; nt < 4; nt++)
                    mma_f16(acc[mt][nt], af[mt], bf[nt]);
        }
        if (it < 31) {
            __half* dA = As + ((it + 1) & 1) * HBUF;
            __half* dW = Ws + ((it + 1) & 1) * HBUF;
            if (!AHALF) {
#pragma unroll
                for (int i = 0; i < 4; i++) {
                    __half2 h0 = __floats2half2_rn(ra[i].x, ra[i].y);
                    __half2 h1 = __floats2half2_rn(ra[i].z, ra[i].w);
                    uint2 u = make_uint2(h2u(h0), h2u(h1));
                    *(uint2*)(dA + (lr + 32 * i) * HPW + lc) = u;
                }
            } else {
#pragma unroll
                for (int i = 0; i < 2; i++) {
                    int c = i * 256 + tid;
                    int r = c >> 2, o8 = (c & 3) * 8;
                    *(uint4*)(dA + r * HPW + o8) = rah[i];
                }
            }
#pragma unroll
            for (int i = 0; i < 4; i++) {
                __half2 h0 = __floats2half2_rn(rw[i].x, rw[i].y);
                __half2 h1 = __floats2half2_rn(rw[i].z, rw[i].w);
                uint2 u = make_uint2(h2u(h0), h2u(h1));
                *(uint2*)(dW + (lr + 32 * i) * HPW + lc) = u;
            }
        }
        __syncthreads();
    }

#pragma unroll
    for (int mt = 0; mt < 4; mt++) {
        int m = m0 + wm + mt * 16 + gi;
#pragma unroll
        for (int nt = 0; nt < 4; nt++) {
            int n = n0 + wn + nt * 8 + 2 * ti;
            float2 bv = *(const float2*)(bias + n);
            float v0x = (acc[mt][nt][0] + bv.x) * scale;
            float v0y = (acc[mt][nt][1] + bv.y) * scale;
            float v1x = (acc[mt][nt][2] + bv.x) * scale;
            float v1y = (acc[mt][nt][3] + bv.y) * scale;
            if (HOUT) {
                *(unsigned*)(Ch + (size_t)m * 1024 + n) = h2u(__floats2half2_rn(v0x, v0y));
                *(unsigned*)(Ch + (size_t)(m + 8) * 1024 + n) = h2u(__floats2half2_rn(v1x, v1y));
            } else {
                *(float2*)(Cf + (size_t)m * 1024 + n) = make_float2(v0x, v0y);
                *(float2*)(Cf + (size_t)(m + 8) * 1024 + n) = make_float2(v1x, v1y);
            }
        }
    }
}

__global__ __launch_bounds__(256, 2) void proj_kernel(
    const float* __restrict__ q_in, const float* __restrict__ k_in,
    const float* __restrict__ v_in, const float* __restrict__ W,
    const float* __restrict__ bias)
{
    extern __shared__ __half smemh[];
    int z = blockIdx.z;
    const float* A = (z == 0) ? q_in : ((z == 1) ? k_in : v_in);
    __half* C = (z == 0) ? g_q : ((z == 1) ? g_k : g_v);
    gemm128h<false, true>(A, nullptr, W + (size_t)z * 1024 * 1024,
                          bias + z * 1024, C, nullptr,
                          (z == 0) ? 0.125f : 1.0f,
                          blockIdx.y * 128, blockIdx.x * 128, smemh);
}

__global__ __launch_bounds__(256, 2) void outproj_kernel(
    const float* __restrict__ W, const float* __restrict__ bias,
    float* __restrict__ out)
{
    extern __shared__ __half smemh[];
    gemm128h<true, false>(nullptr, g_x, W, bias, nullptr, out, 1.0f,
                          blockIdx.y * 128, blockIdx.x * 128, smemh);
}

// ---------------------------------------------------------------------------
// Fused qk+pv kernel: CTA = (bh, 32 t-rows), 2048 CTAs, 256 threads.
// smem: rsbuf[32][4]f + rsinv[32]f | scH[32][1048]h | kv[18432]h | qs[32][72]h
// ---------------------------------------------------------------------------
#define SCHP 1048
#define KHP 72
#define VTP 136
#define ATT_SMEM_BYTES ((32 * 4 + 32) * 4 + (32 * SCHP + 18432 + 32 * KHP) * 2)

__global__ __launch_bounds__(256) void attn_kernel()
{
    extern __shared__ float smf[];
    float* rsbuf = smf;                              // [32][4]
    float* rsinv = smf + 128;                        // [32]
    __half* scH = (__half*)(smf + 160);              // [32][SCHP]
    __half* kv  = scH + 32 * SCHP;                   // K: [2][128][KHP] / V: [2][64][VTP]
    __half* qsH = kv + 18432;                        // [32][KHP]

    int tid = threadIdx.x, lane = tid & 31, wid = tid >> 5;
    int gi = lane >> 2, ti = lane & 3;
    int bh = blockIdx.x >> 5;
    int t0 = (blockIdx.x & 31) * 32;
    int b = bh >> 4, col0 = (bh & 15) * 64;
    int wm = (wid >> 2) * 16, wn = (wid & 3) * 32;

    // ======================= Phase 1: QK + exp =======================
    {
        int r = tid >> 3, o8 = (tid & 7) * 8;
        uint4 qv = *(const uint4*)(g_q + ((size_t)((t0 + r) * 4 + b)) * 1024 + col0 + o8);
        *(uint4*)(qsH + r * KHP + o8) = qv;
    }

    uint4 kr[4];
#pragma unroll
    for (int j = 0; j < 4; j++) {
        int c = j * 256 + tid;
        int r = c >> 3, o8 = (c & 7) * 8;
        kr[j] = *(const uint4*)(g_k + ((size_t)(r * 4 + b)) * 1024 + col0 + o8);
    }
#pragma unroll
    for (int j = 0; j < 4; j++) {
        int c = j * 256 + tid;
        int r = c >> 3, o8 = (c & 7) * 8;
        *(uint4*)(kv + r * KHP + o8) = kr[j];
    }
    __syncthreads();

    unsigned qf[4][4];
#pragma unroll
    for (int kk = 0; kk < 4; kk++) {
        const __half* p = qsH + (wm + gi) * KHP + kk * 16 + 2 * ti;
        qf[kk][0] = *(const unsigned*)(p);
        qf[kk][1] = *(const unsigned*)(p + 8 * KHP);
        qf[kk][2] = *(const unsigned*)(p + 8);
        qf[kk][3] = *(const unsigned*)(p + 8 * KHP + 8);
    }

    float rs0 = 0.f, rs1 = 0.f;   // rowsum partials: rows wm+gi, wm+gi+8

#pragma unroll
    for (int st = 0; st < 8; st++) {
        if (st < 7) {
#pragma unroll
            for (int j = 0; j < 4; j++) {
                int c = j * 256 + tid;
                int r = c >> 3, o8 = (c & 7) * 8;
                kr[j] = *(const uint4*)(g_k + ((size_t)(((st + 1) * 128 + r) * 4 + b)) * 1024 + col0 + o8);
            }
        }
        const __half* buf = kv + (st & 1) * 128 * KHP;
        float acc[4][4];
#pragma unroll
        for (int nt = 0; nt < 4; nt++)
#pragma unroll
            for (int r = 0; r < 4; r++) acc[nt][r] = 0.f;
#pragma unroll
        for (int kk = 0; kk < 4; kk++) {
#pragma unroll
            for (int nt = 0; nt < 4; nt++) {
                unsigned bf[2];
                const __half* p = buf + (wn + nt * 8 + gi) * KHP + kk * 16 + 2 * ti;
                bf[0] = *(const unsigned*)(p);
                bf[1] = *(const unsigned*)(p + 8);
                mma_f16(acc[nt], qf[kk], bf);
            }
        }
        // exp epilogue (FMA-pipe fexp, no MUFU) -> scH fp16 + rowsum partials
#pragma unroll
        for (int nt = 0; nt < 4; nt++) {
            int scol = st * 128 + wn + nt * 8 + 2 * ti;
            float e0 = fexp(acc[nt][0]), e1 = fexp(acc[nt][1]);
            float e2 = fexp(acc[nt][2]), e3 = fexp(acc[nt][3]);
            rs0 += e0 + e1; rs1 += e2 + e3;
            *(unsigned*)(scH + (wm + gi) * SCHP + scol) = h2u(__floats2half2_rn(e0, e1));
            *(unsigned*)(scH + (wm + gi + 8) * SCHP + scol) = h2u(__floats2half2_rn(e2, e3));
        }
        if (st < 7) {
            __half* dst = kv + ((st + 1) & 1) * 128 * KHP;
#pragma unroll
            for (int j = 0; j < 4; j++) {
                int c = j * 256 + tid;
                int r = c >> 3, o8 = (c & 7) * 8;
                *(uint4*)(dst + r * KHP + o8) = kr[j];
            }
        }
        __syncthreads();
    }

    // rowsum: reduce over ti lanes, then over the 4 wn-warps via rsbuf
    rs0 += __shfl_xor_sync(0xffffffffu, rs0, 1, 4);
    rs0 += __shfl_xor_sync(0xffffffffu, rs0, 2, 4);
    rs1 += __shfl_xor_sync(0xffffffffu, rs1, 1, 4);
    rs1 += __shfl_xor_sync(0xffffffffu, rs1, 2, 4);
    if (ti == 0) {
        rsbuf[(wm + gi) * 4 + (wid & 3)] = rs0;
        rsbuf[(wm + gi + 8) * 4 + (wid & 3)] = rs1;
    }
    __syncthreads();
    if (tid < 32) {
        float s = rsbuf[tid * 4] + rsbuf[tid * 4 + 1] +
                  rsbuf[tid * 4 + 2] + rsbuf[tid * 4 + 3];
        float inv = 1.f / s;
        rsinv[tid] = inv;
        g_rs[(size_t)bh * 1024 + t0 + tid] = inv;
    }

    // bulk-copy P~ -> g_p (coalesced uint4) for aw
    {
        __half* gp = g_p + (size_t)bh * (Tl * Sl) + (size_t)t0 * Sl;
#pragma unroll
        for (int i = 0; i < 16; i++) {
            int idx = i * 256 + tid;
            int r = idx >> 7, c8 = (idx & 127) * 8;
            uint4 v = *(const uint4*)(scH + r * SCHP + c8);
            *(uint4*)(gp + (size_t)r * 1024 + c8) = v;
        }
    }

    // ======================= Phase 2: PV =======================
    int wm2 = (wid >> 2) * 16, wn2 = (wid & 3) * 16;
    int vd0 = wid * 8;

    float oacc[2][4];
#pragma unroll
    for (int nt = 0; nt < 2; nt++)
#pragma unroll
        for (int r = 0; r < 4; r++) oacc[nt][r] = 0.f;

    union { uint4 u; __half h[8]; } vv[4];
#pragma unroll
    for (int it = 0; it < 4; it++) {
        int s = lane + it * 32;
        vv[it].u = *(const uint4*)(g_v + ((size_t)(s * 4 + b)) * 1024 + col0 + vd0);
    }
#pragma unroll
    for (int it = 0; it < 4; it++) {
        int s = lane + it * 32;
#pragma unroll
        for (int j = 0; j < 8; j++)
            kv[(vd0 + j) * VTP + s] = vv[it].h[j];
    }
    __syncthreads();

#pragma unroll
    for (int st = 0; st < 8; st++) {
        if (st < 7) {
#pragma unroll
            for (int it = 0; it < 4; it++) {
                int s = (st + 1) * 128 + lane + it * 32;
                vv[it].u = *(const uint4*)(g_v + ((size_t)(s * 4 + b)) * 1024 + col0 + vd0);
            }
        }
        const __half* Vb = kv + (st & 1) * 64 * VTP;
#pragma unroll
        for (int kk = 0; kk < 8; kk++) {
            unsigned af[4];
            const __half* p = scH + (wm2 + gi) * SCHP + st * 128 + kk * 16 + 2 * ti;
            af[0] = *(const unsigned*)(p);
            af[1] = *(const unsigned*)(p + 8 * SCHP);
            af[2] = *(const unsigned*)(p + 8);
            af[3] = *(const unsigned*)(p + 8 * SCHP + 8);
#pragma unroll
            for (int nt = 0; nt < 2; nt++) {
                unsigned bf[2];
                const __half* q = Vb + (wn2 + nt * 8 + gi) * VTP + kk * 16 + 2 * ti;
                bf[0] = *(const unsigned*)(q);
                bf[1] = *(const unsigned*)(q + 8);
                mma_f16(oacc[nt], af, bf);
            }
        }
        if (st < 7) {
            __half* dV = kv + ((st + 1) & 1) * 64 * VTP;
#pragma unroll
            for (int it = 0; it < 4; it++) {
                int s = lane + it * 32;
#pragma unroll
                for (int j = 0; j < 8; j++)
                    dV[(vd0 + j) * VTP + s] = vv[it].h[j];
            }
        }
        __syncthreads();
    }

    {
        int m = t0 + wm2 + gi;
        float w0 = rsinv[wm2 + gi];
        float w1 = rsinv[wm2 + gi + 8];
#pragma unroll
        for (int nt = 0; nt < 2; nt++) {
            int n = col0 + wn2 + nt * 8 + 2 * ti;
            *(unsigned*)(g_x + ((size_t)(m * 4 + b)) * 1024 + n) =
                h2u(__floats2half2_rn(oacc[nt][0] * w0, oacc[nt][1] * w0));
            *(unsigned*)(g_x + ((size_t)((m + 8) * 4 + b)) * 1024 + n) =
                h2u(__floats2half2_rn(oacc[nt][2] * w1, oacc[nt][3] * w1));
        }
    }
}

// ---------------------------------------------------------------------------
// aw_kernel: out_aw[b][t][s] = 1/16 * sum_h P~[b*16+h][t][s] * inv_rs[b*16+h][t]
// ---------------------------------------------------------------------------
__global__ __launch_bounds__(256) void aw_kernel(float* __restrict__ out)
{
    int f = blockIdx.x * 256 + threadIdx.x;     // 4-elem group index, 1M total
    int t = (f >> 8) & 1023;
    int b = f >> 18;                            // 0..3
    int s4 = f & 255;
    const __half* base = g_p + ((size_t)b * 16) * (Tl * Sl) + (size_t)t * 1024 + s4 * 4;
    float ax = 0.f, ay = 0.f, az = 0.f, aw = 0.f;
#pragma unroll
    for (int h = 0; h < 16; h++) {
        float w = g_rs[((size_t)(b * 16 + h)) * 1024 + t] * 0.0625f;
        uint2 u = *reinterpret_cast<const uint2*>(base + (size_t)h * (Tl * Sl));
        float2 f0 = __half22float2(*reinterpret_cast<__half2*>(&u.x));
        float2 f1 = __half22float2(*reinterpret_cast<__half2*>(&u.y));
        ax += f0.x * w; ay += f0.y * w; az += f1.x * w; aw += f1.y * w;
    }
    *(float4*)(out + AW_OFF + (size_t)f * 4) = make_float4(ax, ay, az, aw);
}

// ---------------------------------------------------------------------------

extern "C" void kernel_launch(void* const* d_in, const int* in_sizes, int n_in,
                              void* d_out, int out_size)
{
    const float* query = (const float*)d_in[0];
    const float* key   = (const float*)d_in[1];
    const float* value = (const float*)d_in[2];
    const float* ipw   = (const float*)d_in[3];
    const float* ipb   = (const float*)d_in[4];
    const float* opw   = (const float*)d_in[5];
    const float* opb   = (const float*)d_in[6];
    float* out = (float*)d_out;

    int gemm_smem = 4 * HBUF * sizeof(__half);           // 40,960
    int attn_smem = ATT_SMEM_BYTES;                      // 109,696

    cudaFuncSetAttribute(proj_kernel,
                         cudaFuncAttributeMaxDynamicSharedMemorySize, gemm_smem);
    cudaFuncSetAttribute(outproj_kernel,
                         cudaFuncAttributeMaxDynamicSharedMemorySize, gemm_smem);
    cudaFuncSetAttribute(attn_kernel,
                         cudaFuncAttributeMaxDynamicSharedMemorySize, attn_smem);

    dim3 gp(8, 32, 3);
    proj_kernel<<<gp, 256, gemm_smem>>>(query, key, value, ipw, ipb);

    attn_kernel<<<64 * 32, 256, attn_smem>>>();

    // fork: aw (DRAM-bound) runs concurrently with outproj (tensor-bound)
    cudaEventRecord(g_sx.fork, 0);
    cudaStreamWaitEvent(g_sx.s2, g_sx.fork, 0);
    aw_kernel<<<4096, 256, 0, g_sx.s2>>>(out);
    cudaEventRecord(g_sx.join, g_sx.s2);

    dim3 go(8, 32);
    outproj_kernel<<<go, 256, gemm_smem>>>(opw, opb, out);

    // join: out must be complete before harness reads it
    cudaStreamWaitEvent(0, g_sx.join, 0);
}

// round 15
// speedup vs baseline: 1.0672x; 1.0672x over previous
#include <cuda_runtime.h>
#include <cuda_fp16.h>
#include <math.h>

#define Tl 1024
#define Sl 1024
#define Bb 4
#define Ee 1024
#define Hh 16
#define Dd 64
#define AW_OFF 4194304   // T*B*E

// scratch (device globals) — all fp16
__device__ __half g_q[4096 * 1024];
__device__ __half g_k[4096 * 1024];
__device__ __half g_v[4096 * 1024];
__device__ __half g_x[4096 * 1024];
__device__ __half g_p[64 * 1024 * 1024];  // unnormalized probs [BH][T][S]
__device__ float  g_rs[64 * 1024];        // 1/rowsum [BH][T]

// side stream + events for aw overlap
namespace {
struct StreamInit {
    cudaStream_t s2;
    cudaEvent_t fork, join;
    StreamInit() {
        cudaStreamCreateWithFlags(&s2, cudaStreamNonBlocking);
        cudaEventCreateWithFlags(&fork, cudaEventDisableTiming);
        cudaEventCreateWithFlags(&join, cudaEventDisableTiming);
    }
};
StreamInit g_sx;
}

// ---------------------------------------------------------------------------
__device__ __forceinline__ void mma_f16(float c[4], const unsigned a[4],
                                        const unsigned b[2]) {
    asm volatile(
        "mma.sync.aligned.m16n8k16.row.col.f32.f16.f16.f32 "
        "{%0,%1,%2,%3},{%4,%5,%6,%7},{%8,%9},{%0,%1,%2,%3};"
        : "+f"(c[0]), "+f"(c[1]), "+f"(c[2]), "+f"(c[3])
        : "r"(a[0]), "r"(a[1]), "r"(a[2]), "r"(a[3]), "r"(b[0]), "r"(b[1]));
}
__device__ __forceinline__ unsigned h2u(__half2 h) {
    return *reinterpret_cast<unsigned*>(&h);
}
// 16B async copy global -> shared (no register staging)
__device__ __forceinline__ void cpa16(void* dst_smem, const void* src) {
    unsigned d = (unsigned)__cvta_generic_to_shared(dst_smem);
    asm volatile("cp.async.ca.shared.global [%0], [%1], 16;" :: "r"(d), "l"(src));
}
#define CPA_COMMIT() asm volatile("cp.async.commit_group;" ::: "memory")
#define CPA_WAIT0()  asm volatile("cp.async.wait_group 0;" ::: "memory")

// ---------------------------------------------------------------------------
// fp16 GEMM 128x128xK(1024), 256 threads = 8 warps (2m x 4n), warp 64x32.
// ---------------------------------------------------------------------------
#define HPW 40
#define HBUF (128 * HPW)

template<bool AHALF, bool HOUT>
__device__ __forceinline__ void gemm128h(
    const float* __restrict__ Af, const __half* __restrict__ Ah,
    const float* __restrict__ W, const float* __restrict__ bias,
    __half* __restrict__ Ch, float* __restrict__ Cf,
    float scale, int m0, int n0, __half* smem)
{
    __half* As = smem;                 // [2][HBUF]
    __half* Ws = smem + 2 * HBUF;      // [2][HBUF]

    int tid = threadIdx.x, lane = tid & 31, wid = tid >> 5;
    int gi = lane >> 2, ti = lane & 3;
    int wm = (wid >> 2) * 64, wn = (wid & 3) * 32;
    int lr = tid >> 3, lc = (tid & 7) * 4;

    float acc[4][4][4];
#pragma unroll
    for (int mt = 0; mt < 4; mt++)
#pragma unroll
        for (int nt = 0; nt < 4; nt++)
#pragma unroll
            for (int r = 0; r < 4; r++) acc[mt][nt][r] = 0.f;

    const float* Wg = W + (size_t)(n0 + lr) * 1024 + lc;

    float4 ra[4]; float4 rw[4];
    // ---- prologue: k-step 0 ----
    if (!AHALF) {
#pragma unroll
        for (int i = 0; i < 4; i++)
            ra[i] = *(const float4*)(Af + (size_t)(m0 + lr + 32 * i) * 1024 + lc);
#pragma unroll
        for (int i = 0; i < 4; i++) {
            __half2 h0 = __floats2half2_rn(ra[i].x, ra[i].y);
            __half2 h1 = __floats2half2_rn(ra[i].z, ra[i].w);
            uint2 u = make_uint2(h2u(h0), h2u(h1));
            *(uint2*)(As + (lr + 32 * i) * HPW + lc) = u;
        }
    } else {
#pragma unroll
        for (int i = 0; i < 2; i++) {
            int c = i * 256 + tid;
            int r = c >> 2, o8 = (c & 3) * 8;
            cpa16(As + r * HPW + o8, Ah + (size_t)(m0 + r) * 1024 + o8);
        }
        CPA_COMMIT();
    }
#pragma unroll
    for (int i = 0; i < 4; i++)
        rw[i] = *(const float4*)(Wg + (size_t)i * 32 * 1024);
#pragma unroll
    for (int i = 0; i < 4; i++) {
        __half2 h0 = __floats2half2_rn(rw[i].x, rw[i].y);
        __half2 h1 = __floats2half2_rn(rw[i].z, rw[i].w);
        uint2 u = make_uint2(h2u(h0), h2u(h1));
        *(uint2*)(Ws + (lr + 32 * i) * HPW + lc) = u;
    }
    if (AHALF) CPA_WAIT0();
    __syncthreads();

#pragma unroll 2
    for (int it = 0; it < 32; ++it) {
        if (it < 31) {
            if (!AHALF) {
#pragma unroll
                for (int i = 0; i < 4; i++)
                    ra[i] = *(const float4*)(Af + (size_t)(m0 + lr + 32 * i) * 1024 + (it + 1) * 32 + lc);
            } else {
                __half* dA = As + ((it + 1) & 1) * HBUF;
#pragma unroll
                for (int i = 0; i < 2; i++) {
                    int c = i * 256 + tid;
                    int r = c >> 2, o8 = (c & 3) * 8;
                    cpa16(dA + r * HPW + o8,
                          Ah + (size_t)(m0 + r) * 1024 + (it + 1) * 32 + o8);
                }
                CPA_COMMIT();
            }
#pragma unroll
            for (int i = 0; i < 4; i++)
                rw[i] = *(const float4*)(Wg + (size_t)i * 32 * 1024 + (it + 1) * 32);
        }
        const __half* a_s = As + (it & 1) * HBUF + wm * HPW;
        const __half* b_s = Ws + (it & 1) * HBUF + wn * HPW;
#pragma unroll
        for (int kk = 0; kk < 2; kk++) {
            unsigned af[4][4], bf[4][2];
#pragma unroll
            for (int mt = 0; mt < 4; mt++) {
                const __half* p = a_s + (mt * 16 + gi) * HPW + kk * 16 + 2 * ti;
                af[mt][0] = *(const unsigned*)(p);
                af[mt][1] = *(const unsigned*)(p + 8 * HPW);
                af[mt][2] = *(const unsigned*)(p + 8);
                af[mt][3] = *(const unsigned*)(p + 8 * HPW + 8);
            }
#pragma unroll
            for (int nt = 0; nt < 4; nt++) {
                const __half* p = b_s + (nt * 8 + gi) * HPW + kk * 16 + 2 * ti;
                bf[nt][0] = *(const unsigned*)(p);
                bf[nt][1] = *(const unsigned*)(p + 8);
            }
#pragma unroll
            for (int mt = 0; mt < 4; mt++)
#pragma unroll
                for (int nt = 0; nt < 4; nt++)
                    mma_f16(acc[mt][nt], af[mt], bf[nt]);
        }
        if (it < 31) {
            __half* dA = As + ((it + 1) & 1) * HBUF;
            __half* dW = Ws + ((it + 1) & 1) * HBUF;
            if (!AHALF) {
#pragma unroll
                for (int i = 0; i < 4; i++) {
                    __half2 h0 = __floats2half2_rn(ra[i].x, ra[i].y);
                    __half2 h1 = __floats2half2_rn(ra[i].z, ra[i].w);
                    uint2 u = make_uint2(h2u(h0), h2u(h1));
                    *(uint2*)(dA + (lr + 32 * i) * HPW + lc) = u;
                }
            }
#pragma unroll
            for (int i = 0; i < 4; i++) {
                __half2 h0 = __floats2half2_rn(rw[i].x, rw[i].y);
                __half2 h1 = __floats2half2_rn(rw[i].z, rw[i].w);
                uint2 u = make_uint2(h2u(h0), h2u(h1));
                *(uint2*)(dW + (lr + 32 * i) * HPW + lc) = u;
            }
            if (AHALF) CPA_WAIT0();
        }
        __syncthreads();
    }

#pragma unroll
    for (int mt = 0; mt < 4; mt++) {
        int m = m0 + wm + mt * 16 + gi;
#pragma unroll
        for (int nt = 0; nt < 4; nt++) {
            int n = n0 + wn + nt * 8 + 2 * ti;
            float2 bv = *(const float2*)(bias + n);
            float v0x = (acc[mt][nt][0] + bv.x) * scale;
            float v0y = (acc[mt][nt][1] + bv.y) * scale;
            float v1x = (acc[mt][nt][2] + bv.x) * scale;
            float v1y = (acc[mt][nt][3] + bv.y) * scale;
            if (HOUT) {
                *(unsigned*)(Ch + (size_t)m * 1024 + n) = h2u(__floats2half2_rn(v0x, v0y));
                *(unsigned*)(Ch + (size_t)(m + 8) * 1024 + n) = h2u(__floats2half2_rn(v1x, v1y));
            } else {
                *(float2*)(Cf + (size_t)m * 1024 + n) = make_float2(v0x, v0y);
                *(float2*)(Cf + (size_t)(m + 8) * 1024 + n) = make_float2(v1x, v1y);
            }
        }
    }
}

__global__ __launch_bounds__(256, 2) void proj_kernel(
    const float* __restrict__ q_in, const float* __restrict__ k_in,
    const float* __restrict__ v_in, const float* __restrict__ W,
    const float* __restrict__ bias)
{
    extern __shared__ __half smemh[];
    int z = blockIdx.z;
    const float* A = (z == 0) ? q_in : ((z == 1) ? k_in : v_in);
    __half* C = (z == 0) ? g_q : ((z == 1) ? g_k : g_v);
    gemm128h<false, true>(A, nullptr, W + (size_t)z * 1024 * 1024,
                          bias + z * 1024, C, nullptr,
                          (z == 0) ? 0.125f : 1.0f,
                          blockIdx.y * 128, blockIdx.x * 128, smemh);
}

__global__ __launch_bounds__(256, 2) void outproj_kernel(
    const float* __restrict__ W, const float* __restrict__ bias,
    float* __restrict__ out)
{
    extern __shared__ __half smemh[];
    gemm128h<true, false>(nullptr, g_x, W, bias, nullptr, out, 1.0f,
                          blockIdx.y * 128, blockIdx.x * 128, smemh);
}

// ---------------------------------------------------------------------------
// Fused qk+pv kernel: CTA = (bh, 32 t-rows), 2048 CTAs, 256 threads.
// K tiles loaded via cp.async (raw fp16 copy); V transposed via registers.
// smem: rsbuf[32][4]f + rsinv[32]f | scH[32][1048]h | kv[18432]h | qs[32][72]h
// ---------------------------------------------------------------------------
#define SCHP 1048
#define KHP 72
#define VTP 136
#define ATT_SMEM_BYTES ((32 * 4 + 32) * 4 + (32 * SCHP + 18432 + 32 * KHP) * 2)

__global__ __launch_bounds__(256) void attn_kernel()
{
    extern __shared__ float smf[];
    float* rsbuf = smf;                              // [32][4]
    float* rsinv = smf + 128;                        // [32]
    __half* scH = (__half*)(smf + 160);              // [32][SCHP]
    __half* kv  = scH + 32 * SCHP;                   // K: [2][128][KHP] / V: [2][64][VTP]
    __half* qsH = kv + 18432;                        // [32][KHP]

    int tid = threadIdx.x, lane = tid & 31, wid = tid >> 5;
    int gi = lane >> 2, ti = lane & 3;
    int bh = blockIdx.x >> 5;
    int t0 = (blockIdx.x & 31) * 32;
    int b = bh >> 4, col0 = (bh & 15) * 64;
    int wm = (wid >> 2) * 16, wn = (wid & 3) * 32;

    // ======================= Phase 1: QK + exp =======================
    {
        int r = tid >> 3, o8 = (tid & 7) * 8;
        uint4 qv = *(const uint4*)(g_q + ((size_t)((t0 + r) * 4 + b)) * 1024 + col0 + o8);
        *(uint4*)(qsH + r * KHP + o8) = qv;
    }

    // K prologue: tile 0 via cp.async
#pragma unroll
    for (int j = 0; j < 4; j++) {
        int c = j * 256 + tid;
        int r = c >> 3, o8 = (c & 7) * 8;
        cpa16(kv + r * KHP + o8, g_k + ((size_t)(r * 4 + b)) * 1024 + col0 + o8);
    }
    CPA_COMMIT();
    CPA_WAIT0();
    __syncthreads();

    unsigned qf[4][4];
#pragma unroll
    for (int kk = 0; kk < 4; kk++) {
        const __half* p = qsH + (wm + gi) * KHP + kk * 16 + 2 * ti;
        qf[kk][0] = *(const unsigned*)(p);
        qf[kk][1] = *(const unsigned*)(p + 8 * KHP);
        qf[kk][2] = *(const unsigned*)(p + 8);
        qf[kk][3] = *(const unsigned*)(p + 8 * KHP + 8);
    }

    float rs0 = 0.f, rs1 = 0.f;   // rowsum partials: rows wm+gi, wm+gi+8

#pragma unroll
    for (int st = 0; st < 8; st++) {
        if (st < 7) {
            __half* dst = kv + ((st + 1) & 1) * 128 * KHP;
#pragma unroll
            for (int j = 0; j < 4; j++) {
                int c = j * 256 + tid;
                int r = c >> 3, o8 = (c & 7) * 8;
                cpa16(dst + r * KHP + o8,
                      g_k + ((size_t)(((st + 1) * 128 + r) * 4 + b)) * 1024 + col0 + o8);
            }
            CPA_COMMIT();
        }
        const __half* buf = kv + (st & 1) * 128 * KHP;
        float acc[4][4];
#pragma unroll
        for (int nt = 0; nt < 4; nt++)
#pragma unroll
            for (int r = 0; r < 4; r++) acc[nt][r] = 0.f;
#pragma unroll
        for (int kk = 0; kk < 4; kk++) {
#pragma unroll
            for (int nt = 0; nt < 4; nt++) {
                unsigned bf[2];
                const __half* p = buf + (wn + nt * 8 + gi) * KHP + kk * 16 + 2 * ti;
                bf[0] = *(const unsigned*)(p);
                bf[1] = *(const unsigned*)(p + 8);
                mma_f16(acc[nt], qf[kk], bf);
            }
        }
        // exp epilogue -> scH fp16 + rowsum partials
#pragma unroll
        for (int nt = 0; nt < 4; nt++) {
            int scol = st * 128 + wn + nt * 8 + 2 * ti;
            float e0 = __expf(acc[nt][0]), e1 = __expf(acc[nt][1]);
            float e2 = __expf(acc[nt][2]), e3 = __expf(acc[nt][3]);
            rs0 += e0 + e1; rs1 += e2 + e3;
            *(unsigned*)(scH + (wm + gi) * SCHP + scol) = h2u(__floats2half2_rn(e0, e1));
            *(unsigned*)(scH + (wm + gi + 8) * SCHP + scol) = h2u(__floats2half2_rn(e2, e3));
        }
        if (st < 7) CPA_WAIT0();
        __syncthreads();
    }

    // rowsum: reduce over ti lanes, then over the 4 wn-warps via rsbuf
    rs0 += __shfl_xor_sync(0xffffffffu, rs0, 1, 4);
    rs0 += __shfl_xor_sync(0xffffffffu, rs0, 2, 4);
    rs1 += __shfl_xor_sync(0xffffffffu, rs1, 1, 4);
    rs1 += __shfl_xor_sync(0xffffffffu, rs1, 2, 4);
    if (ti == 0) {
        rsbuf[(wm + gi) * 4 + (wid & 3)] = rs0;
        rsbuf[(wm + gi + 8) * 4 + (wid & 3)] = rs1;
    }
    __syncthreads();
    if (tid < 32) {
        float s = rsbuf[tid * 4] + rsbuf[tid * 4 + 1] +
                  rsbuf[tid * 4 + 2] + rsbuf[tid * 4 + 3];
        float inv = 1.f / s;
        rsinv[tid] = inv;
        g_rs[(size_t)bh * 1024 + t0 + tid] = inv;
    }

    // bulk-copy P~ -> g_p (coalesced uint4) for aw
    {
        __half* gp = g_p + (size_t)bh * (Tl * Sl) + (size_t)t0 * Sl;
#pragma unroll
        for (int i = 0; i < 16; i++) {
            int idx = i * 256 + tid;
            int r = idx >> 7, c8 = (idx & 127) * 8;
            uint4 v = *(const uint4*)(scH + r * SCHP + c8);
            *(uint4*)(gp + (size_t)r * 1024 + c8) = v;
        }
    }

    // ======================= Phase 2: PV =======================
    int wm2 = (wid >> 2) * 16, wn2 = (wid & 3) * 16;
    int vd0 = wid * 8;

    float oacc[2][4];
#pragma unroll
    for (int nt = 0; nt < 2; nt++)
#pragma unroll
        for (int r = 0; r < 4; r++) oacc[nt][r] = 0.f;

    union { uint4 u; __half h[8]; } vv[4];
#pragma unroll
    for (int it = 0; it < 4; it++) {
        int s = lane + it * 32;
        vv[it].u = *(const uint4*)(g_v + ((size_t)(s * 4 + b)) * 1024 + col0 + vd0);
    }
#pragma unroll
    for (int it = 0; it < 4; it++) {
        int s = lane + it * 32;
#pragma unroll
        for (int j = 0; j < 8; j++)
            kv[(vd0 + j) * VTP + s] = vv[it].h[j];
    }
    __syncthreads();

#pragma unroll
    for (int st = 0; st < 8; st++) {
        if (st < 7) {
#pragma unroll
            for (int it = 0; it < 4; it++) {
                int s = (st + 1) * 128 + lane + it * 32;
                vv[it].u = *(const uint4*)(g_v + ((size_t)(s * 4 + b)) * 1024 + col0 + vd0);
            }
        }
        const __half* Vb = kv + (st & 1) * 64 * VTP;
#pragma unroll
        for (int kk = 0; kk < 8; kk++) {
            unsigned af[4];
            const __half* p = scH + (wm2 + gi) * SCHP + st * 128 + kk * 16 + 2 * ti;
            af[0] = *(const unsigned*)(p);
            af[1] = *(const unsigned*)(p + 8 * SCHP);
            af[2] = *(const unsigned*)(p + 8);
            af[3] = *(const unsigned*)(p + 8 * SCHP + 8);
#pragma unroll
            for (int nt = 0; nt < 2; nt++) {
                unsigned bf[2];
                const __half* q = Vb + (wn2 + nt * 8 + gi) * VTP + kk * 16 + 2 * ti;
                bf[0] = *(const unsigned*)(q);
                bf[1] = *(const unsigned*)(q + 8);
                mma_f16(oacc[nt], af, bf);
            }
        }
        if (st < 7) {
            __half* dV = kv + ((st + 1) & 1) * 64 * VTP;
#pragma unroll
            for (int it = 0; it < 4; it++) {
                int s = lane + it * 32;
#pragma unroll
                for (int j = 0; j < 8; j++)
                    dV[(vd0 + j) * VTP + s] = vv[it].h[j];
            }
        }
        __syncthreads();
    }

    {
        int m = t0 + wm2 + gi;
        float w0 = rsinv[wm2 + gi];
        float w1 = rsinv[wm2 + gi + 8];
#pragma unroll
        for (int nt = 0; nt < 2; nt++) {
            int n = col0 + wn2 + nt * 8 + 2 * ti;
            *(unsigned*)(g_x + ((size_t)(m * 4 + b)) * 1024 + n) =
                h2u(__floats2half2_rn(oacc[nt][0] * w0, oacc[nt][1] * w0));
            *(unsigned*)(g_x + ((size_t)((m + 8) * 4 + b)) * 1024 + n) =
                h2u(__floats2half2_rn(oacc[nt][2] * w1, oacc[nt][3] * w1));
        }
    }
}

// ---------------------------------------------------------------------------
// aw_kernel: out_aw[b][t][s] = 1/16 * sum_h P~[b*16+h][t][s] * inv_rs[b*16+h][t]
// ---------------------------------------------------------------------------
__global__ __launch_bounds__(256) void aw_kernel(float* __restrict__ out)
{
    int f = blockIdx.x * 256 + threadIdx.x;     // 4-elem group index, 1M total
    int t = (f >> 8) & 1023;
    int b = f >> 18;                            // 0..3
    int s4 = f & 255;
    const __half* base = g_p + ((size_t)b * 16) * (Tl * Sl) + (size_t)t * 1024 + s4 * 4;
    float ax = 0.f, ay = 0.f, az = 0.f, aw = 0.f;
#pragma unroll
    for (int h = 0; h < 16; h++) {
        float w = g_rs[((size_t)(b * 16 + h)) * 1024 + t] * 0.0625f;
        uint2 u = *reinterpret_cast<const uint2*>(base + (size_t)h * (Tl * Sl));
        float2 f0 = __half22float2(*reinterpret_cast<__half2*>(&u.x));
        float2 f1 = __half22float2(*reinterpret_cast<__half2*>(&u.y));
        ax += f0.x * w; ay += f0.y * w; az += f1.x * w; aw += f1.y * w;
    }
    *(float4*)(out + AW_OFF + (size_t)f * 4) = make_float4(ax, ay, az, aw);
}

// ---------------------------------------------------------------------------

extern "C" void kernel_launch(void* const* d_in, const int* in_sizes, int n_in,
                              void* d_out, int out_size)
{
    const float* query = (const float*)d_in[0];
    const float* key   = (const float*)d_in[1];
    const float* value = (const float*)d_in[2];
    const float* ipw   = (const float*)d_in[3];
    const float* ipb   = (const float*)d_in[4];
    const float* opw   = (const float*)d_in[5];
    const float* opb   = (const float*)d_in[6];
    float* out = (float*)d_out;

    int gemm_smem = 4 * HBUF * sizeof(__half);           // 40,960
    int attn_smem = ATT_SMEM_BYTES;                      // 109,696

    cudaFuncSetAttribute(proj_kernel,
                         cudaFuncAttributeMaxDynamicSharedMemorySize, gemm_smem);
    cudaFuncSetAttribute(outproj_kernel,
                         cudaFuncAttributeMaxDynamicSharedMemorySize, gemm_smem);
    cudaFuncSetAttribute(attn_kernel,
                         cudaFuncAttributeMaxDynamicSharedMemorySize, attn_smem);

    dim3 gp(8, 32, 3);
    proj_kernel<<<gp, 256, gemm_smem>>>(query, key, value, ipw, ipb);

    attn_kernel<<<64 * 32, 256, attn_smem>>>();

    // fork: aw (DRAM-bound) runs concurrently with outproj (tensor-bound)
    cudaEventRecord(g_sx.fork, 0);
    cudaStreamWaitEvent(g_sx.s2, g_sx.fork, 0);
    aw_kernel<<<4096, 256, 0, g_sx.s2>>>(out);
    cudaEventRecord(g_sx.join, g_sx.s2);

    dim3 go(8, 32);
    outproj_kernel<<<go, 256, gemm_smem>>>(opw, opb, out);

    // join: out must be complete before harness reads it
    cudaStreamWaitEvent(0, g_sx.join, 0);
}

// round 16
// speedup vs baseline: 1.1227x; 1.0520x over previous
#include <cuda_runtime.h>
#include <cuda_fp16.h>
#include <math.h>

#define Tl 1024
#define Sl 1024
#define Bb 4
#define Ee 1024
#define Hh 16
#define Dd 64
#define AW_OFF 4194304   // T*B*E

// scratch (device globals) — all fp16
__device__ __half g_q[4096 * 1024];
__device__ __half g_k[4096 * 1024];
__device__ __half g_v[4096 * 1024];
__device__ __half g_x[4096 * 1024];
__device__ __half g_p[64 * 1024 * 1024];  // unnormalized probs [BH][T][S]
__device__ float  g_rs[64 * 1024];        // 1/rowsum [BH][T]
__device__ __half g_in_h[3 * 4194304];    // fp16 copies of query|key|value
__device__ __half g_w_h[4 * 1048576];     // fp16 ipw(3M) | opw(1M)

// side stream + events for aw overlap
namespace {
struct StreamInit {
    cudaStream_t s2;
    cudaEvent_t fork, join;
    StreamInit() {
        cudaStreamCreateWithFlags(&s2, cudaStreamNonBlocking);
        cudaEventCreateWithFlags(&fork, cudaEventDisableTiming);
        cudaEventCreateWithFlags(&join, cudaEventDisableTiming);
    }
};
StreamInit g_sx;
}

// ---------------------------------------------------------------------------
__device__ __forceinline__ void mma_f16(float c[4], const unsigned a[4],
                                        const unsigned b[2]) {
    asm volatile(
        "mma.sync.aligned.m16n8k16.row.col.f32.f16.f16.f32 "
        "{%0,%1,%2,%3},{%4,%5,%6,%7},{%8,%9},{%0,%1,%2,%3};"
        : "+f"(c[0]), "+f"(c[1]), "+f"(c[2]), "+f"(c[3])
        : "r"(a[0]), "r"(a[1]), "r"(a[2]), "r"(a[3]), "r"(b[0]), "r"(b[1]));
}
__device__ __forceinline__ unsigned h2u(__half2 h) {
    return *reinterpret_cast<unsigned*>(&h);
}
// 16B async copy global -> shared (no register staging)
__device__ __forceinline__ void cpa16(void* dst_smem, const void* src) {
    unsigned d = (unsigned)__cvta_generic_to_shared(dst_smem);
    asm volatile("cp.async.ca.shared.global [%0], [%1], 16;" :: "r"(d), "l"(src));
}
#define CPA_COMMIT() asm volatile("cp.async.commit_group;" ::: "memory")
#define CPA_WAIT0()  asm volatile("cp.async.wait_group 0;" ::: "memory")

// ---------------------------------------------------------------------------
// prep: convert inputs + weights to fp16 once. 16,777,216 floats total.
// ---------------------------------------------------------------------------
__global__ __launch_bounds__(256) void prep_kernel(
    const float* __restrict__ q, const float* __restrict__ k,
    const float* __restrict__ v, const float* __restrict__ ipw,
    const float* __restrict__ opw)
{
    int i = (blockIdx.x * 256 + threadIdx.x) * 4;
    const float* src; __half* dst; int off;
    if (i < 4194304)        { src = q;   dst = g_in_h;            off = i; }
    else if (i < 8388608)   { src = k;   dst = g_in_h + 4194304;  off = i - 4194304; }
    else if (i < 12582912)  { src = v;   dst = g_in_h + 8388608;  off = i - 8388608; }
    else if (i < 15728640)  { src = ipw; dst = g_w_h;             off = i - 12582912; }
    else                    { src = opw; dst = g_w_h + 3145728;   off = i - 15728640; }
    float4 fv = *(const float4*)(src + off);
    __half2 h0 = __floats2half2_rn(fv.x, fv.y);
    __half2 h1 = __floats2half2_rn(fv.z, fv.w);
    *(uint2*)(dst + off) = make_uint2(h2u(h0), h2u(h1));
}

// ---------------------------------------------------------------------------
// fp16 GEMM 128x128xK(1024), 256 threads = 8 warps (2m x 4n), warp 64x32.
// Both operands fp16 via cp.async.
// ---------------------------------------------------------------------------
#define HPW 40
#define HBUF (128 * HPW)

template<bool HOUT>
__device__ __forceinline__ void gemm128h(
    const __half* __restrict__ Ah, const __half* __restrict__ Wh,
    const float* __restrict__ bias,
    __half* __restrict__ Ch, float* __restrict__ Cf,
    float scale, int m0, int n0, __half* smem)
{
    __half* As = smem;                 // [2][HBUF]
    __half* Ws = smem + 2 * HBUF;      // [2][HBUF]

    int tid = threadIdx.x, lane = tid & 31, wid = tid >> 5;
    int gi = lane >> 2, ti = lane & 3;
    int wm = (wid >> 2) * 64, wn = (wid & 3) * 32;

    float acc[4][4][4];
#pragma unroll
    for (int mt = 0; mt < 4; mt++)
#pragma unroll
        for (int nt = 0; nt < 4; nt++)
#pragma unroll
            for (int r = 0; r < 4; r++) acc[mt][nt][r] = 0.f;

    // prologue: stage 0 (A + W via cp.async)
#pragma unroll
    for (int i = 0; i < 2; i++) {
        int c = i * 256 + tid;
        int r = c >> 2, o8 = (c & 3) * 8;
        cpa16(As + r * HPW + o8, Ah + (size_t)(m0 + r) * 1024 + o8);
        cpa16(Ws + r * HPW + o8, Wh + (size_t)(n0 + r) * 1024 + o8);
    }
    CPA_COMMIT();
    CPA_WAIT0();
    __syncthreads();

#pragma unroll 2
    for (int it = 0; it < 32; ++it) {
        if (it < 31) {
            __half* dA = As + ((it + 1) & 1) * HBUF;
            __half* dW = Ws + ((it + 1) & 1) * HBUF;
#pragma unroll
            for (int i = 0; i < 2; i++) {
                int c = i * 256 + tid;
                int r = c >> 2, o8 = (c & 3) * 8;
                cpa16(dA + r * HPW + o8, Ah + (size_t)(m0 + r) * 1024 + (it + 1) * 32 + o8);
                cpa16(dW + r * HPW + o8, Wh + (size_t)(n0 + r) * 1024 + (it + 1) * 32 + o8);
            }
            CPA_COMMIT();
        }
        const __half* a_s = As + (it & 1) * HBUF + wm * HPW;
        const __half* b_s = Ws + (it & 1) * HBUF + wn * HPW;
#pragma unroll
        for (int kk = 0; kk < 2; kk++) {
            unsigned af[4][4], bf[4][2];
#pragma unroll
            for (int mt = 0; mt < 4; mt++) {
                const __half* p = a_s + (mt * 16 + gi) * HPW + kk * 16 + 2 * ti;
                af[mt][0] = *(const unsigned*)(p);
                af[mt][1] = *(const unsigned*)(p + 8 * HPW);
                af[mt][2] = *(const unsigned*)(p + 8);
                af[mt][3] = *(const unsigned*)(p + 8 * HPW + 8);
            }
#pragma unroll
            for (int nt = 0; nt < 4; nt++) {
                const __half* p = b_s + (nt * 8 + gi) * HPW + kk * 16 + 2 * ti;
                bf[nt][0] = *(const unsigned*)(p);
                bf[nt][1] = *(const unsigned*)(p + 8);
            }
#pragma unroll
            for (int mt = 0; mt < 4; mt++)
#pragma unroll
                for (int nt = 0; nt < 4; nt++)
                    mma_f16(acc[mt][nt], af[mt], bf[nt]);
        }
        if (it < 31) CPA_WAIT0();
        __syncthreads();
    }

#pragma unroll
    for (int mt = 0; mt < 4; mt++) {
        int m = m0 + wm + mt * 16 + gi;
#pragma unroll
        for (int nt = 0; nt < 4; nt++) {
            int n = n0 + wn + nt * 8 + 2 * ti;
            float2 bv = *(const float2*)(bias + n);
            float v0x = (acc[mt][nt][0] + bv.x) * scale;
            float v0y = (acc[mt][nt][1] + bv.y) * scale;
            float v1x = (acc[mt][nt][2] + bv.x) * scale;
            float v1y = (acc[mt][nt][3] + bv.y) * scale;
            if (HOUT) {
                *(unsigned*)(Ch + (size_t)m * 1024 + n) = h2u(__floats2half2_rn(v0x, v0y));
                *(unsigned*)(Ch + (size_t)(m + 8) * 1024 + n) = h2u(__floats2half2_rn(v1x, v1y));
            } else {
                *(float2*)(Cf + (size_t)m * 1024 + n) = make_float2(v0x, v0y);
                *(float2*)(Cf + (size_t)(m + 8) * 1024 + n) = make_float2(v1x, v1y);
            }
        }
    }
}

__global__ __launch_bounds__(256, 2) void proj_kernel(const float* __restrict__ bias)
{
    extern __shared__ __half smemh[];
    int z = blockIdx.z;
    __half* C = (z == 0) ? g_q : ((z == 1) ? g_k : g_v);
    gemm128h<true>(g_in_h + (size_t)z * 4194304, g_w_h + (size_t)z * 1048576,
                   bias + z * 1024, C, nullptr,
                   (z == 0) ? 0.125f : 1.0f,
                   blockIdx.y * 128, blockIdx.x * 128, smemh);
}

__global__ __launch_bounds__(256, 2) void outproj_kernel(
    const float* __restrict__ bias, float* __restrict__ out)
{
    extern __shared__ __half smemh[];
    gemm128h<false>(g_x, g_w_h + 3145728, bias, nullptr, out, 1.0f,
                    blockIdx.y * 128, blockIdx.x * 128, smemh);
}

// ---------------------------------------------------------------------------
// Fused qk+pv kernel: CTA = (bh, 32 t-rows), 2048 CTAs, 256 threads.
// K tiles via cp.async; V transposed via registers.
// smem: rsbuf[32][4]f + rsinv[32]f | scH[32][1048]h | kv[18432]h | qs[32][72]h
// ---------------------------------------------------------------------------
#define SCHP 1048
#define KHP 72
#define VTP 136
#define ATT_SMEM_BYTES ((32 * 4 + 32) * 4 + (32 * SCHP + 18432 + 32 * KHP) * 2)

__global__ __launch_bounds__(256) void attn_kernel()
{
    extern __shared__ float smf[];
    float* rsbuf = smf;                              // [32][4]
    float* rsinv = smf + 128;                        // [32]
    __half* scH = (__half*)(smf + 160);              // [32][SCHP]
    __half* kv  = scH + 32 * SCHP;                   // K: [2][128][KHP] / V: [2][64][VTP]
    __half* qsH = kv + 18432;                        // [32][KHP]

    int tid = threadIdx.x, lane = tid & 31, wid = tid >> 5;
    int gi = lane >> 2, ti = lane & 3;
    int bh = blockIdx.x >> 5;
    int t0 = (blockIdx.x & 31) * 32;
    int b = bh >> 4, col0 = (bh & 15) * 64;
    int wm = (wid >> 2) * 16, wn = (wid & 3) * 32;

    // ======================= Phase 1: QK + exp =======================
    {
        int r = tid >> 3, o8 = (tid & 7) * 8;
        uint4 qv = *(const uint4*)(g_q + ((size_t)((t0 + r) * 4 + b)) * 1024 + col0 + o8);
        *(uint4*)(qsH + r * KHP + o8) = qv;
    }

    // K prologue: tile 0 via cp.async
#pragma unroll
    for (int j = 0; j < 4; j++) {
        int c = j * 256 + tid;
        int r = c >> 3, o8 = (c & 7) * 8;
        cpa16(kv + r * KHP + o8, g_k + ((size_t)(r * 4 + b)) * 1024 + col0 + o8);
    }
    CPA_COMMIT();
    CPA_WAIT0();
    __syncthreads();

    unsigned qf[4][4];
#pragma unroll
    for (int kk = 0; kk < 4; kk++) {
        const __half* p = qsH + (wm + gi) * KHP + kk * 16 + 2 * ti;
        qf[kk][0] = *(const unsigned*)(p);
        qf[kk][1] = *(const unsigned*)(p + 8 * KHP);
        qf[kk][2] = *(const unsigned*)(p + 8);
        qf[kk][3] = *(const unsigned*)(p + 8 * KHP + 8);
    }

    float rs0 = 0.f, rs1 = 0.f;   // rowsum partials: rows wm+gi, wm+gi+8

#pragma unroll
    for (int st = 0; st < 8; st++) {
        if (st < 7) {
            __half* dst = kv + ((st + 1) & 1) * 128 * KHP;
#pragma unroll
            for (int j = 0; j < 4; j++) {
                int c = j * 256 + tid;
                int r = c >> 3, o8 = (c & 7) * 8;
                cpa16(dst + r * KHP + o8,
                      g_k + ((size_t)(((st + 1) * 128 + r) * 4 + b)) * 1024 + col0 + o8);
            }
            CPA_COMMIT();
        }
        const __half* buf = kv + (st & 1) * 128 * KHP;
        float acc[4][4];
#pragma unroll
        for (int nt = 0; nt < 4; nt++)
#pragma unroll
            for (int r = 0; r < 4; r++) acc[nt][r] = 0.f;
#pragma unroll
        for (int kk = 0; kk < 4; kk++) {
#pragma unroll
            for (int nt = 0; nt < 4; nt++) {
                unsigned bf[2];
                const __half* p = buf + (wn + nt * 8 + gi) * KHP + kk * 16 + 2 * ti;
                bf[0] = *(const unsigned*)(p);
                bf[1] = *(const unsigned*)(p + 8);
                mma_f16(acc[nt], qf[kk], bf);
            }
        }
        // exp epilogue -> scH fp16 + rowsum partials
#pragma unroll
        for (int nt = 0; nt < 4; nt++) {
            int scol = st * 128 + wn + nt * 8 + 2 * ti;
            float e0 = __expf(acc[nt][0]), e1 = __expf(acc[nt][1]);
            float e2 = __expf(acc[nt][2]), e3 = __expf(acc[nt][3]);
            rs0 += e0 + e1; rs1 += e2 + e3;
            *(unsigned*)(scH + (wm + gi) * SCHP + scol) = h2u(__floats2half2_rn(e0, e1));
            *(unsigned*)(scH + (wm + gi + 8) * SCHP + scol) = h2u(__floats2half2_rn(e2, e3));
        }
        if (st < 7) CPA_WAIT0();
        __syncthreads();
    }

    // rowsum: reduce over ti lanes, then over the 4 wn-warps via rsbuf
    rs0 += __shfl_xor_sync(0xffffffffu, rs0, 1, 4);
    rs0 += __shfl_xor_sync(0xffffffffu, rs0, 2, 4);
    rs1 += __shfl_xor_sync(0xffffffffu, rs1, 1, 4);
    rs1 += __shfl_xor_sync(0xffffffffu, rs1, 2, 4);
    if (ti == 0) {
        rsbuf[(wm + gi) * 4 + (wid & 3)] = rs0;
        rsbuf[(wm + gi + 8) * 4 + (wid & 3)] = rs1;
    }
    __syncthreads();
    if (tid < 32) {
        float s = rsbuf[tid * 4] + rsbuf[tid * 4 + 1] +
                  rsbuf[tid * 4 + 2] + rsbuf[tid * 4 + 3];
        float inv = 1.f / s;
        rsinv[tid] = inv;
        g_rs[(size_t)bh * 1024 + t0 + tid] = inv;
    }

    // bulk-copy P~ -> g_p (coalesced uint4) for aw
    {
        __half* gp = g_p + (size_t)bh * (Tl * Sl) + (size_t)t0 * Sl;
#pragma unroll
        for (int i = 0; i < 16; i++) {
            int idx = i * 256 + tid;
            int r = idx >> 7, c8 = (idx & 127) * 8;
            uint4 v = *(const uint4*)(scH + r * SCHP + c8);
            *(uint4*)(gp + (size_t)r * 1024 + c8) = v;
        }
    }

    // ======================= Phase 2: PV =======================
    int wm2 = (wid >> 2) * 16, wn2 = (wid & 3) * 16;
    int vd0 = wid * 8;

    float oacc[2][4];
#pragma unroll
    for (int nt = 0; nt < 2; nt++)
#pragma unroll
        for (int r = 0; r < 4; r++) oacc[nt][r] = 0.f;

    union { uint4 u; __half h[8]; } vv[4];
#pragma unroll
    for (int it = 0; it < 4; it++) {
        int s = lane + it * 32;
        vv[it].u = *(const uint4*)(g_v + ((size_t)(s * 4 + b)) * 1024 + col0 + vd0);
    }
#pragma unroll
    for (int it = 0; it < 4; it++) {
        int s = lane + it * 32;
#pragma unroll
        for (int j = 0; j < 8; j++)
            kv[(vd0 + j) * VTP + s] = vv[it].h[j];
    }
    __syncthreads();

#pragma unroll
    for (int st = 0; st < 8; st++) {
        if (st < 7) {
#pragma unroll
            for (int it = 0; it < 4; it++) {
                int s = (st + 1) * 128 + lane + it * 32;
                vv[it].u = *(const uint4*)(g_v + ((size_t)(s * 4 + b)) * 1024 + col0 + vd0);
            }
        }
        const __half* Vb = kv + (st & 1) * 64 * VTP;
#pragma unroll
        for (int kk = 0; kk < 8; kk++) {
            unsigned af[4];
            const __half* p = scH + (wm2 + gi) * SCHP + st * 128 + kk * 16 + 2 * ti;
            af[0] = *(const unsigned*)(p);
            af[1] = *(const unsigned*)(p + 8 * SCHP);
            af[2] = *(const unsigned*)(p + 8);
            af[3] = *(const unsigned*)(p + 8 * SCHP + 8);
#pragma unroll
            for (int nt = 0; nt < 2; nt++) {
                unsigned bf[2];
                const __half* q = Vb + (wn2 + nt * 8 + gi) * VTP + kk * 16 + 2 * ti;
                bf[0] = *(const unsigned*)(q);
                bf[1] = *(const unsigned*)(q + 8);
                mma_f16(oacc[nt], af, bf);
            }
        }
        if (st < 7) {
            __half* dV = kv + ((st + 1) & 1) * 64 * VTP;
#pragma unroll
            for (int it = 0; it < 4; it++) {
                int s = lane + it * 32;
#pragma unroll
                for (int j = 0; j < 8; j++)
                    dV[(vd0 + j) * VTP + s] = vv[it].h[j];
            }
        }
        __syncthreads();
    }

    {
        int m = t0 + wm2 + gi;
        float w0 = rsinv[wm2 + gi];
        float w1 = rsinv[wm2 + gi + 8];
#pragma unroll
        for (int nt = 0; nt < 2; nt++) {
            int n = col0 + wn2 + nt * 8 + 2 * ti;
            *(unsigned*)(g_x + ((size_t)(m * 4 + b)) * 1024 + n) =
                h2u(__floats2half2_rn(oacc[nt][0] * w0, oacc[nt][1] * w0));
            *(unsigned*)(g_x + ((size_t)((m + 8) * 4 + b)) * 1024 + n) =
                h2u(__floats2half2_rn(oacc[nt][2] * w1, oacc[nt][3] * w1));
        }
    }
}

// ---------------------------------------------------------------------------
// aw_kernel: out_aw[b][t][s] = 1/16 * sum_h P~[b*16+h][t][s] * inv_rs[b*16+h][t]
// ---------------------------------------------------------------------------
__global__ __launch_bounds__(256) void aw_kernel(float* __restrict__ out)
{
    int f = blockIdx.x * 256 + threadIdx.x;     // 4-elem group index, 1M total
    int t = (f >> 8) & 1023;
    int b = f >> 18;                            // 0..3
    int s4 = f & 255;
    const __half* base = g_p + ((size_t)b * 16) * (Tl * Sl) + (size_t)t * 1024 + s4 * 4;
    float ax = 0.f, ay = 0.f, az = 0.f, aw = 0.f;
#pragma unroll
    for (int h = 0; h < 16; h++) {
        float w = g_rs[((size_t)(b * 16 + h)) * 1024 + t] * 0.0625f;
        uint2 u = *reinterpret_cast<const uint2*>(base + (size_t)h * (Tl * Sl));
        float2 f0 = __half22float2(*reinterpret_cast<__half2*>(&u.x));
        float2 f1 = __half22float2(*reinterpret_cast<__half2*>(&u.y));
        ax += f0.x * w; ay += f0.y * w; az += f1.x * w; aw += f1.y * w;
    }
    *(float4*)(out + AW_OFF + (size_t)f * 4) = make_float4(ax, ay, az, aw);
}

// ---------------------------------------------------------------------------

extern "C" void kernel_launch(void* const* d_in, const int* in_sizes, int n_in,
                              void* d_out, int out_size)
{
    const float* query = (const float*)d_in[0];
    const float* key   = (const float*)d_in[1];
    const float* value = (const float*)d_in[2];
    const float* ipw   = (const float*)d_in[3];
    const float* ipb   = (const float*)d_in[4];
    const float* opw   = (const float*)d_in[5];
    const float* opb   = (const float*)d_in[6];
    float* out = (float*)d_out;

    int gemm_smem = 4 * HBUF * sizeof(__half);           // 40,960
    int attn_smem = ATT_SMEM_BYTES;                      // 109,696

    cudaFuncSetAttribute(proj_kernel,
                         cudaFuncAttributeMaxDynamicSharedMemorySize, gemm_smem);
    cudaFuncSetAttribute(outproj_kernel,
                         cudaFuncAttributeMaxDynamicSharedMemorySize, gemm_smem);
    cudaFuncSetAttribute(attn_kernel,
                         cudaFuncAttributeMaxDynamicSharedMemorySize, attn_smem);

    prep_kernel<<<16384, 256>>>(query, key, value, ipw, opw);

    dim3 gp(8, 32, 3);
    proj_kernel<<<gp, 256, gemm_smem>>>(ipb);

    attn_kernel<<<64 * 32, 256, attn_smem>>>();

    // fork: aw (DRAM-bound) runs concurrently with outproj (tensor-bound)
    cudaEventRecord(g_sx.fork, 0);
    cudaStreamWaitEvent(g_sx.s2, g_sx.fork, 0);
    aw_kernel<<<4096, 256, 0, g_sx.s2>>>(out);
    cudaEventRecord(g_sx.join, g_sx.s2);

    dim3 go(8, 32);
    outproj_kernel<<<go, 256, gemm_smem>>>(opb, out);

    // join: out must be complete before harness reads it
    cudaStreamWaitEvent(0, g_sx.join, 0);
}

// round 17
// speedup vs baseline: 1.1943x; 1.0638x over previous
#include <cuda_runtime.h>
#include <cuda_fp16.h>
#include <math.h>

#define Tl 1024
#define Sl 1024
#define Bb 4
#define Ee 1024
#define Hh 16
#define Dd 64
#define AW_OFF 4194304   // T*B*E

// scratch (device globals) — all fp16
__device__ __half g_q[4096 * 1024];
__device__ __half g_k[4096 * 1024];
__device__ __half g_v[4096 * 1024];
__device__ __half g_x[4096 * 1024];
__device__ __half g_p[64 * 1024 * 1024];  // unnormalized probs [BH][T][S]
__device__ float  g_rs[64 * 1024];        // 1/rowsum [BH][T]
__device__ __half g_in_h[3 * 4194304];    // fp16 copies of query|key|value
__device__ __half g_w_h[4 * 1048576];     // fp16 ipw(3M) | opw(1M)

// side stream + events for aw overlap
namespace {
struct StreamInit {
    cudaStream_t s2;
    cudaEvent_t fork, join;
    StreamInit() {
        cudaStreamCreateWithFlags(&s2, cudaStreamNonBlocking);
        cudaEventCreateWithFlags(&fork, cudaEventDisableTiming);
        cudaEventCreateWithFlags(&join, cudaEventDisableTiming);
    }
};
StreamInit g_sx;
}

// ---------------------------------------------------------------------------
__device__ __forceinline__ void mma_f16(float c[4], const unsigned a[4],
                                        const unsigned b[2]) {
    asm volatile(
        "mma.sync.aligned.m16n8k16.row.col.f32.f16.f16.f32 "
        "{%0,%1,%2,%3},{%4,%5,%6,%7},{%8,%9},{%0,%1,%2,%3};"
        : "+f"(c[0]), "+f"(c[1]), "+f"(c[2]), "+f"(c[3])
        : "r"(a[0]), "r"(a[1]), "r"(a[2]), "r"(a[3]), "r"(b[0]), "r"(b[1]));
}
__device__ __forceinline__ unsigned h2u(__half2 h) {
    return *reinterpret_cast<unsigned*>(&h);
}
// 16B async copy global -> shared (no register staging)
__device__ __forceinline__ void cpa16(void* dst_smem, const void* src) {
    unsigned d = (unsigned)__cvta_generic_to_shared(dst_smem);
    asm volatile("cp.async.ca.shared.global [%0], [%1], 16;" :: "r"(d), "l"(src));
}
#define CPA_COMMIT() asm volatile("cp.async.commit_group;" ::: "memory")
#define CPA_WAIT0()  asm volatile("cp.async.wait_group 0;" ::: "memory")

// ---------------------------------------------------------------------------
// prep: convert inputs + weights to fp16 once. 16,777,216 floats total.
// ---------------------------------------------------------------------------
__global__ __launch_bounds__(256) void prep_kernel(
    const float* __restrict__ q, const float* __restrict__ k,
    const float* __restrict__ v, const float* __restrict__ ipw,
    const float* __restrict__ opw)
{
    int i = (blockIdx.x * 256 + threadIdx.x) * 4;
    const float* src; __half* dst; int off;
    if (i < 4194304)        { src = q;   dst = g_in_h;            off = i; }
    else if (i < 8388608)   { src = k;   dst = g_in_h + 4194304;  off = i - 4194304; }
    else if (i < 12582912)  { src = v;   dst = g_in_h + 8388608;  off = i - 8388608; }
    else if (i < 15728640)  { src = ipw; dst = g_w_h;             off = i - 12582912; }
    else                    { src = opw; dst = g_w_h + 3145728;   off = i - 15728640; }
    float4 fv = *(const float4*)(src + off);
    __half2 h0 = __floats2half2_rn(fv.x, fv.y);
    __half2 h1 = __floats2half2_rn(fv.z, fv.w);
    *(uint2*)(dst + off) = make_uint2(h2u(h0), h2u(h1));
}

// ---------------------------------------------------------------------------
// fp16 GEMM 128x128xK(1024), 256 threads = 8 warps (2m x 4n), warp 64x32.
// K-step 64 (16 iterations, doubled copy-latency window). Pitch 72 halves
// (36 words; gi*36+ti == gi*4+ti distinct mod 32 -> conflict-free).
// ---------------------------------------------------------------------------
#define HPW 72
#define HBUF (128 * HPW)

template<bool HOUT>
__device__ __forceinline__ void gemm128h(
    const __half* __restrict__ Ah, const __half* __restrict__ Wh,
    const float* __restrict__ bias,
    __half* __restrict__ Ch, float* __restrict__ Cf,
    float scale, int m0, int n0, __half* smem)
{
    __half* As = smem;                 // [2][HBUF]
    __half* Ws = smem + 2 * HBUF;      // [2][HBUF]

    int tid = threadIdx.x, lane = tid & 31, wid = tid >> 5;
    int gi = lane >> 2, ti = lane & 3;
    int wm = (wid >> 2) * 64, wn = (wid & 3) * 32;

    float acc[4][4][4];
#pragma unroll
    for (int mt = 0; mt < 4; mt++)
#pragma unroll
        for (int nt = 0; nt < 4; nt++)
#pragma unroll
            for (int r = 0; r < 4; r++) acc[mt][nt][r] = 0.f;

    // prologue: stage 0 (A + W via cp.async; 128x64 fp16 each)
#pragma unroll
    for (int i = 0; i < 4; i++) {
        int c = i * 256 + tid;
        int r = c >> 3, o8 = (c & 7) * 8;
        cpa16(As + r * HPW + o8, Ah + (size_t)(m0 + r) * 1024 + o8);
        cpa16(Ws + r * HPW + o8, Wh + (size_t)(n0 + r) * 1024 + o8);
    }
    CPA_COMMIT();
    CPA_WAIT0();
    __syncthreads();

#pragma unroll 2
    for (int it = 0; it < 16; ++it) {
        if (it < 15) {
            __half* dA = As + ((it + 1) & 1) * HBUF;
            __half* dW = Ws + ((it + 1) & 1) * HBUF;
#pragma unroll
            for (int i = 0; i < 4; i++) {
                int c = i * 256 + tid;
                int r = c >> 3, o8 = (c & 7) * 8;
                cpa16(dA + r * HPW + o8, Ah + (size_t)(m0 + r) * 1024 + (it + 1) * 64 + o8);
                cpa16(dW + r * HPW + o8, Wh + (size_t)(n0 + r) * 1024 + (it + 1) * 64 + o8);
            }
            CPA_COMMIT();
        }
        const __half* a_s = As + (it & 1) * HBUF + wm * HPW;
        const __half* b_s = Ws + (it & 1) * HBUF + wn * HPW;
#pragma unroll
        for (int kk = 0; kk < 4; kk++) {
            unsigned af[4][4], bf[4][2];
#pragma unroll
            for (int mt = 0; mt < 4; mt++) {
                const __half* p = a_s + (mt * 16 + gi) * HPW + kk * 16 + 2 * ti;
                af[mt][0] = *(const unsigned*)(p);
                af[mt][1] = *(const unsigned*)(p + 8 * HPW);
                af[mt][2] = *(const unsigned*)(p + 8);
                af[mt][3] = *(const unsigned*)(p + 8 * HPW + 8);
            }
#pragma unroll
            for (int nt = 0; nt < 4; nt++) {
                const __half* p = b_s + (nt * 8 + gi) * HPW + kk * 16 + 2 * ti;
                bf[nt][0] = *(const unsigned*)(p);
                bf[nt][1] = *(const unsigned*)(p + 8);
            }
#pragma unroll
            for (int mt = 0; mt < 4; mt++)
#pragma unroll
                for (int nt = 0; nt < 4; nt++)
                    mma_f16(acc[mt][nt], af[mt], bf[nt]);
        }
        if (it < 15) CPA_WAIT0();
        __syncthreads();
    }

#pragma unroll
    for (int mt = 0; mt < 4; mt++) {
        int m = m0 + wm + mt * 16 + gi;
#pragma unroll
        for (int nt = 0; nt < 4; nt++) {
            int n = n0 + wn + nt * 8 + 2 * ti;
            float2 bv = *(const float2*)(bias + n);
            float v0x = (acc[mt][nt][0] + bv.x) * scale;
            float v0y = (acc[mt][nt][1] + bv.y) * scale;
            float v1x = (acc[mt][nt][2] + bv.x) * scale;
            float v1y = (acc[mt][nt][3] + bv.y) * scale;
            if (HOUT) {
                *(unsigned*)(Ch + (size_t)m * 1024 + n) = h2u(__floats2half2_rn(v0x, v0y));
                *(unsigned*)(Ch + (size_t)(m + 8) * 1024 + n) = h2u(__floats2half2_rn(v1x, v1y));
            } else {
                *(float2*)(Cf + (size_t)m * 1024 + n) = make_float2(v0x, v0y);
                *(float2*)(Cf + (size_t)(m + 8) * 1024 + n) = make_float2(v1x, v1y);
            }
        }
    }
}

__global__ __launch_bounds__(256) void proj_kernel(const float* __restrict__ bias)
{
    extern __shared__ __half smemh[];
    int z = blockIdx.z;
    __half* C = (z == 0) ? g_q : ((z == 1) ? g_k : g_v);
    gemm128h<true>(g_in_h + (size_t)z * 4194304, g_w_h + (size_t)z * 1048576,
                   bias + z * 1024, C, nullptr,
                   (z == 0) ? 0.125f : 1.0f,
                   blockIdx.y * 128, blockIdx.x * 128, smemh);
}

__global__ __launch_bounds__(256) void outproj_kernel(
    const float* __restrict__ bias, float* __restrict__ out)
{
    extern __shared__ __half smemh[];
    gemm128h<false>(g_x, g_w_h + 3145728, bias, nullptr, out, 1.0f,
                    blockIdx.y * 128, blockIdx.x * 128, smemh);
}

// ---------------------------------------------------------------------------
// Fused qk+pv kernel: CTA = (bh, 32 t-rows), 2048 CTAs, 256 threads.
// K tiles via cp.async; V transposed via registers.
// smem: rsbuf[32][4]f + rsinv[32]f | scH[32][1048]h | kv[18432]h | qs[32][72]h
// ---------------------------------------------------------------------------
#define SCHP 1048
#define KHP 72
#define VTP 136
#define ATT_SMEM_BYTES ((32 * 4 + 32) * 4 + (32 * SCHP + 18432 + 32 * KHP) * 2)

__global__ __launch_bounds__(256) void attn_kernel()
{
    extern __shared__ float smf[];
    float* rsbuf = smf;                              // [32][4]
    float* rsinv = smf + 128;                        // [32]
    __half* scH = (__half*)(smf + 160);              // [32][SCHP]
    __half* kv  = scH + 32 * SCHP;                   // K: [2][128][KHP] / V: [2][64][VTP]
    __half* qsH = kv + 18432;                        // [32][KHP]

    int tid = threadIdx.x, lane = tid & 31, wid = tid >> 5;
    int gi = lane >> 2, ti = lane & 3;
    int bh = blockIdx.x >> 5;
    int t0 = (blockIdx.x & 31) * 32;
    int b = bh >> 4, col0 = (bh & 15) * 64;
    int wm = (wid >> 2) * 16, wn = (wid & 3) * 32;

    // ======================= Phase 1: QK + exp =======================
    {
        int r = tid >> 3, o8 = (tid & 7) * 8;
        uint4 qv = *(const uint4*)(g_q + ((size_t)((t0 + r) * 4 + b)) * 1024 + col0 + o8);
        *(uint4*)(qsH + r * KHP + o8) = qv;
    }

    // K prologue: tile 0 via cp.async
#pragma unroll
    for (int j = 0; j < 4; j++) {
        int c = j * 256 + tid;
        int r = c >> 3, o8 = (c & 7) * 8;
        cpa16(kv + r * KHP + o8, g_k + ((size_t)(r * 4 + b)) * 1024 + col0 + o8);
    }
    CPA_COMMIT();
    CPA_WAIT0();
    __syncthreads();

    unsigned qf[4][4];
#pragma unroll
    for (int kk = 0; kk < 4; kk++) {
        const __half* p = qsH + (wm + gi) * KHP + kk * 16 + 2 * ti;
        qf[kk][0] = *(const unsigned*)(p);
        qf[kk][1] = *(const unsigned*)(p + 8 * KHP);
        qf[kk][2] = *(const unsigned*)(p + 8);
        qf[kk][3] = *(const unsigned*)(p + 8 * KHP + 8);
    }

    float rs0 = 0.f, rs1 = 0.f;   // rowsum partials: rows wm+gi, wm+gi+8

#pragma unroll
    for (int st = 0; st < 8; st++) {
        if (st < 7) {
            __half* dst = kv + ((st + 1) & 1) * 128 * KHP;
#pragma unroll
            for (int j = 0; j < 4; j++) {
                int c = j * 256 + tid;
                int r = c >> 3, o8 = (c & 7) * 8;
                cpa16(dst + r * KHP + o8,
                      g_k + ((size_t)(((st + 1) * 128 + r) * 4 + b)) * 1024 + col0 + o8);
            }
            CPA_COMMIT();
        }
        const __half* buf = kv + (st & 1) * 128 * KHP;
        float acc[4][4];
#pragma unroll
        for (int nt = 0; nt < 4; nt++)
#pragma unroll
            for (int r = 0; r < 4; r++) acc[nt][r] = 0.f;
#pragma unroll
        for (int kk = 0; kk < 4; kk++) {
#pragma unroll
            for (int nt = 0; nt < 4; nt++) {
                unsigned bf[2];
                const __half* p = buf + (wn + nt * 8 + gi) * KHP + kk * 16 + 2 * ti;
                bf[0] = *(const unsigned*)(p);
                bf[1] = *(const unsigned*)(p + 8);
                mma_f16(acc[nt], qf[kk], bf);
            }
        }
        // exp epilogue -> scH fp16 + rowsum partials
#pragma unroll
        for (int nt = 0; nt < 4; nt++) {
            int scol = st * 128 + wn + nt * 8 + 2 * ti;
            float e0 = __expf(acc[nt][0]), e1 = __expf(acc[nt][1]);
            float e2 = __expf(acc[nt][2]), e3 = __expf(acc[nt][3]);
            rs0 += e0 + e1; rs1 += e2 + e3;
            *(unsigned*)(scH + (wm + gi) * SCHP + scol) = h2u(__floats2half2_rn(e0, e1));
            *(unsigned*)(scH + (wm + gi + 8) * SCHP + scol) = h2u(__floats2half2_rn(e2, e3));
        }
        if (st < 7) CPA_WAIT0();
        __syncthreads();
    }

    // rowsum: reduce over ti lanes, then over the 4 wn-warps via rsbuf
    rs0 += __shfl_xor_sync(0xffffffffu, rs0, 1, 4);
    rs0 += __shfl_xor_sync(0xffffffffu, rs0, 2, 4);
    rs1 += __shfl_xor_sync(0xffffffffu, rs1, 1, 4);
    rs1 += __shfl_xor_sync(0xffffffffu, rs1, 2, 4);
    if (ti == 0) {
        rsbuf[(wm + gi) * 4 + (wid & 3)] = rs0;
        rsbuf[(wm + gi + 8) * 4 + (wid & 3)] = rs1;
    }
    __syncthreads();
    if (tid < 32) {
        float s = rsbuf[tid * 4] + rsbuf[tid * 4 + 1] +
                  rsbuf[tid * 4 + 2] + rsbuf[tid * 4 + 3];
        float inv = 1.f / s;
        rsinv[tid] = inv;
        g_rs[(size_t)bh * 1024 + t0 + tid] = inv;
    }

    // bulk-copy P~ -> g_p (coalesced uint4) for aw
    {
        __half* gp = g_p + (size_t)bh * (Tl * Sl) + (size_t)t0 * Sl;
#pragma unroll
        for (int i = 0; i < 16; i++) {
            int idx = i * 256 + tid;
            int r = idx >> 7, c8 = (idx & 127) * 8;
            uint4 v = *(const uint4*)(scH + r * SCHP + c8);
            *(uint4*)(gp + (size_t)r * 1024 + c8) = v;
        }
    }

    // ======================= Phase 2: PV =======================
    int wm2 = (wid >> 2) * 16, wn2 = (wid & 3) * 16;
    int vd0 = wid * 8;

    float oacc[2][4];
#pragma unroll
    for (int nt = 0; nt < 2; nt++)
#pragma unroll
        for (int r = 0; r < 4; r++) oacc[nt][r] = 0.f;

    union { uint4 u; __half h[8]; } vv[4];
#pragma unroll
    for (int it = 0; it < 4; it++) {
        int s = lane + it * 32;
        vv[it].u = *(const uint4*)(g_v + ((size_t)(s * 4 + b)) * 1024 + col0 + vd0);
    }
#pragma unroll
    for (int it = 0; it < 4; it++) {
        int s = lane + it * 32;
#pragma unroll
        for (int j = 0; j < 8; j++)
            kv[(vd0 + j) * VTP + s] = vv[it].h[j];
    }
    __syncthreads();

#pragma unroll
    for (int st = 0; st < 8; st++) {
        if (st < 7) {
#pragma unroll
            for (int it = 0; it < 4; it++) {
                int s = (st + 1) * 128 + lane + it * 32;
                vv[it].u = *(const uint4*)(g_v + ((size_t)(s * 4 + b)) * 1024 + col0 + vd0);
            }
        }
        const __half* Vb = kv + (st & 1) * 64 * VTP;
#pragma unroll
        for (int kk = 0; kk < 8; kk++) {
            unsigned af[4];
            const __half* p = scH + (wm2 + gi) * SCHP + st * 128 + kk * 16 + 2 * ti;
            af[0] = *(const unsigned*)(p);
            af[1] = *(const unsigned*)(p + 8 * SCHP);
            af[2] = *(const unsigned*)(p + 8);
            af[3] = *(const unsigned*)(p + 8 * SCHP + 8);
#pragma unroll
            for (int nt = 0; nt < 2; nt++) {
                unsigned bf[2];
                const __half* q = Vb + (wn2 + nt * 8 + gi) * VTP + kk * 16 + 2 * ti;
                bf[0] = *(const unsigned*)(q);
                bf[1] = *(const unsigned*)(q + 8);
                mma_f16(oacc[nt], af, bf);
            }
        }
        if (st < 7) {
            __half* dV = kv + ((st + 1) & 1) * 64 * VTP;
#pragma unroll
            for (int it = 0; it < 4; it++) {
                int s = lane + it * 32;
#pragma unroll
                for (int j = 0; j < 8; j++)
                    dV[(vd0 + j) * VTP + s] = vv[it].h[j];
            }
        }
        __syncthreads();
    }

    {
        int m = t0 + wm2 + gi;
        float w0 = rsinv[wm2 + gi];
        float w1 = rsinv[wm2 + gi + 8];
#pragma unroll
        for (int nt = 0; nt < 2; nt++) {
            int n = col0 + wn2 + nt * 8 + 2 * ti;
            *(unsigned*)(g_x + ((size_t)(m * 4 + b)) * 1024 + n) =
                h2u(__floats2half2_rn(oacc[nt][0] * w0, oacc[nt][1] * w0));
            *(unsigned*)(g_x + ((size_t)((m + 8) * 4 + b)) * 1024 + n) =
                h2u(__floats2half2_rn(oacc[nt][2] * w1, oacc[nt][3] * w1));
        }
    }
}

// ---------------------------------------------------------------------------
// aw_kernel: out_aw[b][t][s] = 1/16 * sum_h P~[b*16+h][t][s] * inv_rs[b*16+h][t]
// ---------------------------------------------------------------------------
__global__ __launch_bounds__(256) void aw_kernel(float* __restrict__ out)
{
    int f = blockIdx.x * 256 + threadIdx.x;     // 4-elem group index, 1M total
    int t = (f >> 8) & 1023;
    int b = f >> 18;                            // 0..3
    int s4 = f & 255;
    const __half* base = g_p + ((size_t)b * 16) * (Tl * Sl) + (size_t)t * 1024 + s4 * 4;
    float ax = 0.f, ay = 0.f, az = 0.f, aw = 0.f;
#pragma unroll
    for (int h = 0; h < 16; h++) {
        float w = g_rs[((size_t)(b * 16 + h)) * 1024 + t] * 0.0625f;
        uint2 u = *reinterpret_cast<const uint2*>(base + (size_t)h * (Tl * Sl));
        float2 f0 = __half22float2(*reinterpret_cast<__half2*>(&u.x));
        float2 f1 = __half22float2(*reinterpret_cast<__half2*>(&u.y));
        ax += f0.x * w; ay += f0.y * w; az += f1.x * w; aw += f1.y * w;
    }
    *(float4*)(out + AW_OFF + (size_t)f * 4) = make_float4(ax, ay, az, aw);
}

// ---------------------------------------------------------------------------

extern "C" void kernel_launch(void* const* d_in, const int* in_sizes, int n_in,
                              void* d_out, int out_size)
{
    const float* query = (const float*)d_in[0];
    const float* key   = (const float*)d_in[1];
    const float* value = (const float*)d_in[2];
    const float* ipw   = (const float*)d_in[3];
    const float* ipb   = (const float*)d_in[4];
    const float* opw   = (const float*)d_in[5];
    const float* opb   = (const float*)d_in[6];
    float* out = (float*)d_out;

    int gemm_smem = 4 * HBUF * sizeof(__half);           // 73,728
    int attn_smem = ATT_SMEM_BYTES;                      // 109,696

    cudaFuncSetAttribute(proj_kernel,
                         cudaFuncAttributeMaxDynamicSharedMemorySize, gemm_smem);
    cudaFuncSetAttribute(outproj_kernel,
                         cudaFuncAttributeMaxDynamicSharedMemorySize, gemm_smem);
    cudaFuncSetAttribute(attn_kernel,
                         cudaFuncAttributeMaxDynamicSharedMemorySize, attn_smem);

    prep_kernel<<<16384, 256>>>(query, key, value, ipw, opw);

    dim3 gp(8, 32, 3);
    proj_kernel<<<gp, 256, gemm_smem>>>(ipb);

    attn_kernel<<<64 * 32, 256, attn_smem>>>();

    // fork: aw (DRAM-bound) runs concurrently with outproj (tensor-bound)
    cudaEventRecord(g_sx.fork, 0);
    cudaStreamWaitEvent(g_sx.s2, g_sx.fork, 0);
    aw_kernel<<<4096, 256, 0, g_sx.s2>>>(out);
    cudaEventRecord(g_sx.join, g_sx.s2);

    dim3 go(8, 32);
    outproj_kernel<<<go, 256, gemm_smem>>>(opb, out);

    // join: out must be complete before harness reads it
    cudaStreamWaitEvent(0, g_sx.join, 0);
}